// round 5
// baseline (speedup 1.0000x reference)
#include <cuda_runtime.h>
#include <math.h>

#define POOL 7
#define C 256

typedef unsigned long long u64;

__device__ __forceinline__ u64 f32x2_mul(u64 a, u64 b) {
    u64 d; asm("mul.rn.f32x2 %0, %1, %2;" : "=l"(d) : "l"(a), "l"(b)); return d;
}
__device__ __forceinline__ u64 f32x2_fma(u64 a, u64 b, u64 c) {
    u64 d; asm("fma.rn.f32x2 %0, %1, %2, %3;" : "=l"(d) : "l"(a), "l"(b), "l"(c)); return d;
}
__device__ __forceinline__ u64 f32x2_pack(float v) {
    u64 d; asm("mov.b64 %0, {%1, %1};" : "=l"(d) : "f"(v)); return d;
}
__device__ __forceinline__ u64 bilerp2(u64 v00, u64 v01, u64 v10, u64 v11,
                                       u64 wtx2, u64 tx2, u64 wty2, u64 ty2) {
    u64 top = f32x2_fma(v01, tx2, f32x2_mul(v00, wtx2));
    u64 bot = f32x2_fma(v11, tx2, f32x2_mul(v10, wtx2));
    return f32x2_fma(bot, ty2, f32x2_mul(top, wty2));
}

// Non-sinkable 128-bit load: ptxas must issue these in program order,
// so a batch of 16 stays a batch (true MLP-16 per thread).
#define LDG128(v, p) \
    asm volatile("ld.global.nc.v2.u64 {%0,%1}, [%2];" \
                 : "=l"((v).x), "=l"((v).y) : "l"(p))

// One block per ROI. Block (32,7): warp = pooled row, lane = channel quad
// (each lane covers quads lane and lane+32). Cells processed in pairs with
// 16 batched volatile loads per pair.
__global__ __launch_bounds__(224, 3)
void roi_align_kernel(const float* __restrict__ rois,
                      const int*   __restrict__ image_shape,
                      const float* __restrict__ p2,
                      const float* __restrict__ p3,
                      const float* __restrict__ p4,
                      const float* __restrict__ p5,
                      float* __restrict__ out,
                      int N)
{
    const int bn = blockIdx.x;
    const int b  = bn / N;

    const float4 r = reinterpret_cast<const float4*>(rois)[bn];
    const float y1 = r.x, x1 = r.y, y2 = r.z, x2 = r.w;
    const float h = y2 - y1;
    const float w = x2 - x1;

    const float img_area = (float)(image_shape[0]) * (float)(image_shape[1]);
    const float scale = sqrtf(fmaxf(h * w, 1e-12f)) * (sqrtf(img_area) / 224.0f);
    int lvl = 4 + (int)rintf(log2f(scale));   // round-half-even == jnp.round
    lvl = min(max(lvl, 2), 5);

    const float* feat;
    int H;
    switch (lvl) {
        case 2:  feat = p2; H = 256; break;
        case 3:  feat = p3; H = 128; break;
        case 4:  feat = p4; H = 64;  break;
        default: feat = p5; H = 32;  break;
    }
    const float Hm1 = (float)(H - 1);
    const float Hm2 = (float)(H - 2);
    feat += (size_t)b * (size_t)H * (size_t)H * C;

    const int lane = threadIdx.x;   // channel quad (and +32)
    const int py   = threadIdx.y;   // pooled row (warp-uniform)

    // y coordinate (warp-uniform)
    const float gy  = (float)py * (1.0f / (POOL - 1));
    const float ysf = (y1 + gy * h) * Hm1;
    const float y0f = fminf(fmaxf(floorf(ysf), 0.0f), Hm2);
    const int   y0  = (int)y0f;
    const float ty  = fminf(fmaxf(ysf - y0f, 0.0f), 1.0f);
    const u64 wty2 = f32x2_pack(1.0f - ty);
    const u64 ty2  = f32x2_pack(ty);

    // Row bases in 16B quads; +lane gives this thread's slot.
    const ulonglong2* row0 = reinterpret_cast<const ulonglong2*>(feat) +
                             (size_t)y0 * H * 64 + lane;
    const ulonglong2* row1 = row0 + (size_t)H * 64;

    // Precompute 7 x offsets (quad units) + fractions.
    int   xo[POOL];
    float txa[POOL];
#pragma unroll
    for (int px = 0; px < POOL; ++px) {
        const float gx  = (float)px * (1.0f / (POOL - 1));
        const float xsf = (x1 + gx * w) * Hm1;
        const float x0f = fminf(fmaxf(floorf(xsf), 0.0f), Hm2);
        xo[px]  = (int)x0f * 64;
        txa[px] = fminf(fmaxf(xsf - x0f, 0.0f), 1.0f);
    }

    float4* out_base = reinterpret_cast<float4*>(out + (size_t)bn * (POOL * POOL * C))
                       + (size_t)py * POOL * 64 + lane;

    // ---- paired cells: 16 batched loads, then compute both ----
#pragma unroll
    for (int g = 0; g < 3; ++g) {
        const int pxA = 2 * g;
        const int pxB = 2 * g + 1;
        const ulonglong2* A0 = row0 + xo[pxA];
        const ulonglong2* A1 = row1 + xo[pxA];
        const ulonglong2* B0 = row0 + xo[pxB];
        const ulonglong2* B1 = row1 + xo[pxB];

        // offsets (16B units): +0 = v00(lane), +32 = v00(lane+32),
        //                      +64 = v01(lane), +96 = v01(lane+32)
        ulonglong2 a00, a00h, a01, a01h, a10, a10h, a11, a11h;
        ulonglong2 c00, c00h, c01, c01h, c10, c10h, c11, c11h;
        LDG128(a00,  A0);      LDG128(a00h, A0 + 32);
        LDG128(a01,  A0 + 64); LDG128(a01h, A0 + 96);
        LDG128(a10,  A1);      LDG128(a10h, A1 + 32);
        LDG128(a11,  A1 + 64); LDG128(a11h, A1 + 96);
        LDG128(c00,  B0);      LDG128(c00h, B0 + 32);
        LDG128(c01,  B0 + 64); LDG128(c01h, B0 + 96);
        LDG128(c10,  B1);      LDG128(c10h, B1 + 32);
        LDG128(c11,  B1 + 64); LDG128(c11h, B1 + 96);

        {
            const float tx = txa[pxA];
            const u64 wtx2 = f32x2_pack(1.0f - tx);
            const u64 tx2  = f32x2_pack(tx);
            ulonglong2 ra, rb;
            ra.x = bilerp2(a00.x,  a01.x,  a10.x,  a11.x,  wtx2, tx2, wty2, ty2);
            ra.y = bilerp2(a00.y,  a01.y,  a10.y,  a11.y,  wtx2, tx2, wty2, ty2);
            rb.x = bilerp2(a00h.x, a01h.x, a10h.x, a11h.x, wtx2, tx2, wty2, ty2);
            rb.y = bilerp2(a00h.y, a01h.y, a10h.y, a11h.y, wtx2, tx2, wty2, ty2);
            __stcs(out_base + pxA * 64,      *reinterpret_cast<float4*>(&ra));
            __stcs(out_base + pxA * 64 + 32, *reinterpret_cast<float4*>(&rb));
        }
        {
            const float tx = txa[pxB];
            const u64 wtx2 = f32x2_pack(1.0f - tx);
            const u64 tx2  = f32x2_pack(tx);
            ulonglong2 ra, rb;
            ra.x = bilerp2(c00.x,  c01.x,  c10.x,  c11.x,  wtx2, tx2, wty2, ty2);
            ra.y = bilerp2(c00.y,  c01.y,  c10.y,  c11.y,  wtx2, tx2, wty2, ty2);
            rb.x = bilerp2(c00h.x, c01h.x, c10h.x, c11h.x, wtx2, tx2, wty2, ty2);
            rb.y = bilerp2(c00h.y, c01h.y, c10h.y, c11h.y, wtx2, tx2, wty2, ty2);
            __stcs(out_base + pxB * 64,      *reinterpret_cast<float4*>(&ra));
            __stcs(out_base + pxB * 64 + 32, *reinterpret_cast<float4*>(&rb));
        }
    }

    // ---- tail cell px=6 ----
    {
        const ulonglong2* A0 = row0 + xo[6];
        const ulonglong2* A1 = row1 + xo[6];
        ulonglong2 a00, a00h, a01, a01h, a10, a10h, a11, a11h;
        LDG128(a00,  A0);      LDG128(a00h, A0 + 32);
        LDG128(a01,  A0 + 64); LDG128(a01h, A0 + 96);
        LDG128(a10,  A1);      LDG128(a10h, A1 + 32);
        LDG128(a11,  A1 + 64); LDG128(a11h, A1 + 96);

        const float tx = txa[6];
        const u64 wtx2 = f32x2_pack(1.0f - tx);
        const u64 tx2  = f32x2_pack(tx);
        ulonglong2 ra, rb;
        ra.x = bilerp2(a00.x,  a01.x,  a10.x,  a11.x,  wtx2, tx2, wty2, ty2);
        ra.y = bilerp2(a00.y,  a01.y,  a10.y,  a11.y,  wtx2, tx2, wty2, ty2);
        rb.x = bilerp2(a00h.x, a01h.x, a10h.x, a11h.x, wtx2, tx2, wty2, ty2);
        rb.y = bilerp2(a00h.y, a01h.y, a10h.y, a11h.y, wtx2, tx2, wty2, ty2);
        __stcs(out_base + 6 * 64,      *reinterpret_cast<float4*>(&ra));
        __stcs(out_base + 6 * 64 + 32, *reinterpret_cast<float4*>(&rb));
    }
}

extern "C" void kernel_launch(void* const* d_in, const int* in_sizes, int n_in,
                              void* d_out, int out_size)
{
    const float* rois        = (const float*)d_in[0];
    const int*   image_shape = (const int*)  d_in[1];
    const float* p2          = (const float*)d_in[2];
    const float* p3          = (const float*)d_in[3];
    const float* p4          = (const float*)d_in[4];
    const float* p5          = (const float*)d_in[5];
    float*       out         = (float*)d_out;

    const int B = in_sizes[2] / (256 * 256 * 256);
    const int N = in_sizes[0] / (4 * B);

    dim3 block(32, 7);
    dim3 grid(B * N);
    roi_align_kernel<<<grid, block>>>(rois, image_shape, p2, p3, p4, p5, out, N);
}

// round 6
// speedup vs baseline: 1.1405x; 1.1405x over previous
#include <cuda_runtime.h>
#include <math.h>

#define POOL 7
#define C 256

typedef unsigned long long u64;

__device__ __forceinline__ u64 f32x2_mul(u64 a, u64 b) {
    u64 d; asm("mul.rn.f32x2 %0, %1, %2;" : "=l"(d) : "l"(a), "l"(b)); return d;
}
__device__ __forceinline__ u64 f32x2_fma(u64 a, u64 b, u64 c) {
    u64 d; asm("fma.rn.f32x2 %0, %1, %2, %3;" : "=l"(d) : "l"(a), "l"(b), "l"(c)); return d;
}
__device__ __forceinline__ u64 f32x2_pack(float v) {
    u64 d; asm("mov.b64 %0, {%1, %1};" : "=l"(d) : "f"(v)); return d;
}
__device__ __forceinline__ u64 bilerp2(u64 v00, u64 v01, u64 v10, u64 v11,
                                       u64 wtx2, u64 tx2, u64 wty2, u64 ty2) {
    u64 top = f32x2_fma(v01, tx2, f32x2_mul(v00, wtx2));
    u64 bot = f32x2_fma(v11, tx2, f32x2_mul(v10, wtx2));
    return f32x2_fma(bot, ty2, f32x2_mul(top, wty2));
}

// One block per ROI. Block (32,7): warp = pooled row, lane = channel quad
// (covers quads lane and lane+32). Column-carry: since x0[] is non-decreasing
// and block-uniform, walking px left->right lets each cell reuse the previous
// cell's right column as its left column (register shift), cutting requested
// read bytes ~40-45%. All carry branches are warp-uniform (no divergence).
__global__ __launch_bounds__(224, 4)
void roi_align_kernel(const float* __restrict__ rois,
                      const int*   __restrict__ image_shape,
                      const float* __restrict__ p2,
                      const float* __restrict__ p3,
                      const float* __restrict__ p4,
                      const float* __restrict__ p5,
                      float* __restrict__ out,
                      int N)
{
    const int bn = blockIdx.x;
    const int b  = bn / N;

    const float4 r = reinterpret_cast<const float4*>(rois)[bn];
    const float y1 = r.x, x1 = r.y, y2 = r.z, x2 = r.w;
    const float h = y2 - y1;
    const float w = x2 - x1;

    const float img_area = (float)(image_shape[0]) * (float)(image_shape[1]);
    const float scale = sqrtf(fmaxf(h * w, 1e-12f)) * (sqrtf(img_area) / 224.0f);
    int lvl = 4 + (int)rintf(log2f(scale));   // round-half-even == jnp.round
    lvl = min(max(lvl, 2), 5);

    const float* feat;
    int H;
    switch (lvl) {
        case 2:  feat = p2; H = 256; break;
        case 3:  feat = p3; H = 128; break;
        case 4:  feat = p4; H = 64;  break;
        default: feat = p5; H = 32;  break;
    }
    const float Hm1 = (float)(H - 1);
    const float Hm2 = (float)(H - 2);
    feat += (size_t)b * (size_t)H * (size_t)H * C;

    const int lane = threadIdx.x;   // channel quad (and +32)
    const int py   = threadIdx.y;   // pooled row (warp-uniform)

    // ---- y coordinate (warp-uniform) ----
    const float gy  = (float)py * (1.0f / (POOL - 1));
    const float ysf = (y1 + gy * h) * Hm1;
    const float y0f = fminf(fmaxf(floorf(ysf), 0.0f), Hm2);
    const int   y0  = (int)y0f;
    const float ty  = fminf(fmaxf(ysf - y0f, 0.0f), 1.0f);
    const u64 wty2 = f32x2_pack(1.0f - ty);
    const u64 ty2  = f32x2_pack(ty);

    // Row bases in 16B quads; +lane gives this thread's slot.
    const ulonglong2* row0 = reinterpret_cast<const ulonglong2*>(feat) +
                             (size_t)y0 * H * 64 + lane;
    const ulonglong2* row1 = row0 + (size_t)H * 64;

    // ---- precompute 7 x offsets (quad units, non-decreasing) + fractions ----
    int   xo[POOL];
    float txa[POOL];
#pragma unroll
    for (int px = 0; px < POOL; ++px) {
        const float gx  = (float)px * (1.0f / (POOL - 1));
        const float xsf = (x1 + gx * w) * Hm1;
        const float x0f = fminf(fmaxf(floorf(xsf), 0.0f), Hm2);
        xo[px]  = (int)x0f * 64;
        txa[px] = fminf(fmaxf(xsf - x0f, 0.0f), 1.0f);
    }

    float4* out_base = reinterpret_cast<float4*>(out + (size_t)bn * (POOL * POOL * C))
                       + (size_t)py * POOL * 64 + lane;

    // Column-carry state: columns (cx, cx+1) for rows y0, y0+1; a = quad lane,
    // b = quad lane+32.
    ulonglong2 s00a, s00b, s01a, s01b, s10a, s10b, s11a, s11b;
    int cx = -128;   // sentinel: forces full load at px=0

#pragma unroll
    for (int px = 0; px < POOL; ++px) {
        const int x = xo[px];
        if (x == cx + 64) {
            // shift right column -> left, load one new column (4 LDG.128)
            s00a = s01a; s00b = s01b;
            s10a = s11a; s10b = s11b;
            const ulonglong2* p0 = row0 + (x + 64);
            const ulonglong2* p1 = row1 + (x + 64);
            s01a = p0[0]; s01b = p0[32];
            s11a = p1[0]; s11b = p1[32];
        } else if (x != cx) {
            // fresh pair of columns (8 LDG.128)
            const ulonglong2* p0 = row0 + x;
            const ulonglong2* p1 = row1 + x;
            s00a = p0[0];  s00b = p0[32];
            s01a = p0[64]; s01b = p0[96];
            s10a = p1[0];  s10b = p1[32];
            s11a = p1[64]; s11b = p1[96];
        }
        cx = x;

        const float tx = txa[px];
        const u64 wtx2 = f32x2_pack(1.0f - tx);
        const u64 tx2  = f32x2_pack(tx);

        ulonglong2 ra, rb;
        ra.x = bilerp2(s00a.x, s01a.x, s10a.x, s11a.x, wtx2, tx2, wty2, ty2);
        ra.y = bilerp2(s00a.y, s01a.y, s10a.y, s11a.y, wtx2, tx2, wty2, ty2);
        rb.x = bilerp2(s00b.x, s01b.x, s10b.x, s11b.x, wtx2, tx2, wty2, ty2);
        rb.y = bilerp2(s00b.y, s01b.y, s10b.y, s11b.y, wtx2, tx2, wty2, ty2);

        __stcs(out_base + px * 64,      *reinterpret_cast<float4*>(&ra));
        __stcs(out_base + px * 64 + 32, *reinterpret_cast<float4*>(&rb));
    }
}

extern "C" void kernel_launch(void* const* d_in, const int* in_sizes, int n_in,
                              void* d_out, int out_size)
{
    const float* rois        = (const float*)d_in[0];
    const int*   image_shape = (const int*)  d_in[1];
    const float* p2          = (const float*)d_in[2];
    const float* p3          = (const float*)d_in[3];
    const float* p4          = (const float*)d_in[4];
    const float* p5          = (const float*)d_in[5];
    float*       out         = (float*)d_out;

    const int B = in_sizes[2] / (256 * 256 * 256);
    const int N = in_sizes[0] / (4 * B);

    dim3 block(32, 7);
    dim3 grid(B * N);
    roi_align_kernel<<<grid, block>>>(rois, image_shape, p2, p3, p4, p5, out, N);
}